// round 7
// baseline (speedup 1.0000x reference)
#include <cuda_runtime.h>
#include <cuda_bf16.h>
#include <cstdint>

#define PK      16
#define NCENT   8192
#define IN_F    64
#define OUT_F   128
#define M_TILE  64
#define NTH     512
#define LDB     144          // smem row pitch bytes (64 bf16 + 8 pad)

// pre-split, pre-transposed weights: Wt[k][o][i] = W[k][i][o] as bf16 hi/lo
__device__ __align__(128) __nv_bfloat16 g_wt_hi[PK * OUT_F * IN_F];
__device__ __align__(128) __nv_bfloat16 g_wt_lo[PK * OUT_F * IN_F];

// ---------------- smem layout (bytes), single stage (PROVEN in R5) ----------
#define SM_KPTS   0                        // 48 floats
#define SM_COEF   256                      // 64*16 f32 = 4096
#define SM_SRCS   (SM_COEF + 4096)         // 64*16 int = 4096
#define SM_TILES  8704
#define A_BYTES   (M_TILE * LDB)           // 9216
#define B_BYTES   (OUT_F * LDB)            // 18432
#define AH_OFF    SM_TILES
#define AL_OFF    (AH_OFF + A_BYTES)
#define BH_OFF    (AL_OFF + A_BYTES)
#define BL_OFF    (BH_OFF + B_BYTES)
#define SM_TOTAL  (BL_OFF + B_BYTES)       // 64000

// ---------------- PTX helpers ------------------------------------------------
__device__ __forceinline__ uint32_t smem_u32(const void* p) {
    uint32_t a;
    asm("{ .reg .u64 t; cvta.to.shared.u64 t, %1; cvt.u32.u64 %0, t; }"
        : "=r"(a) : "l"(p));
    return a;
}
__device__ __forceinline__ void ldsm4(uint32_t* r, uint32_t addr) {
    asm volatile("ldmatrix.sync.aligned.m8n8.x4.shared.b16 {%0,%1,%2,%3}, [%4];"
                 : "=r"(r[0]), "=r"(r[1]), "=r"(r[2]), "=r"(r[3]) : "r"(addr));
}
__device__ __forceinline__ void mma_bf16(float* c, const uint32_t* a, const uint32_t* b) {
    asm volatile("mma.sync.aligned.m16n8k16.row.col.f32.bf16.bf16.f32 "
                 "{%0,%1,%2,%3}, {%4,%5,%6,%7}, {%8,%9}, {%0,%1,%2,%3};"
                 : "+f"(c[0]), "+f"(c[1]), "+f"(c[2]), "+f"(c[3])
                 : "r"(a[0]), "r"(a[1]), "r"(a[2]), "r"(a[3]),
                   "r"(b[0]), "r"(b[1]));
}

// ---------------- pre-kernel: W -> Wt_hi/Wt_lo -------------------------------
__global__ void wsplit_kernel(const float* __restrict__ w) {
    int idx = blockIdx.x * blockDim.x + threadIdx.x;
    if (idx >= PK * OUT_F * IN_F) return;
    int k = idx >> 13, rem = idx & 8191;
    int o = rem >> 6, i = rem & 63;
    float v = w[k * (IN_F * OUT_F) + i * OUT_F + o];
    __nv_bfloat16 h = __float2bfloat16(v);
    g_wt_hi[idx] = h;
    g_wt_lo[idx] = __float2bfloat16(v - __bfloat162float(h));
}

// ---------------- main fused kernel ------------------------------------------
__global__ __launch_bounds__(NTH, 1) void kpconv_hmma_kernel(
    const float* __restrict__ x,
    const float* __restrict__ pos,
    const int*   __restrict__ edge_src,
    const int*   __restrict__ edge_tgt,
    const float* __restrict__ kernel_pts,
    float* __restrict__ out)
{
    extern __shared__ char sm[];
    const uint32_t smb = smem_u32(sm);
    float* s_kpts = (float*)(sm + SM_KPTS);
    float* s_coef = (float*)(sm + SM_COEF);
    int*   s_srcs = (int*)(sm + SM_SRCS);

    const int tid  = threadIdx.x;
    const int wid  = tid >> 5;
    const int lane = tid & 31;
    const int c0   = blockIdx.x * M_TILE;

    if (tid < PK * 3) s_kpts[tid] = kernel_pts[tid];
    for (int i = tid; i < M_TILE * PK; i += NTH) s_coef[i] = 0.0f;
    __syncthreads();

    // ---- geometry: argmin kernel point + linear influence -> coef/srcs -----
    #pragma unroll
    for (int j = 0; j < (M_TILE * PK) / NTH; j++) {
        int el = tid + j * NTH;                 // local edge 0..1023
        int e  = c0 * PK + el;
        int s  = edge_src[e];
        int t  = edge_tgt[e];
        s_srcs[el] = s;
        float rx = pos[3 * t + 0] - pos[3 * s + 0];
        float ry = pos[3 * t + 1] - pos[3 * s + 1];
        float rz = pos[3 * t + 2] - pos[3 * s + 2];
        float best = 3.4e38f; int bk = 0;
        #pragma unroll
        for (int kp = 0; kp < PK; kp++) {
            float dx = rx - s_kpts[3 * kp + 0];
            float dy = ry - s_kpts[3 * kp + 1];
            float dz = rz - s_kpts[3 * kp + 2];
            float d2 = dx * dx + dy * dy + dz * dz;
            if (d2 < best) { best = d2; bk = kp; }
        }
        float w = fmaxf(1.0f - sqrtf(best) * 1.5f, 0.0f);   // 1/KP_EXTENT = 1.5
        atomicAdd(&s_coef[(el & ~(PK - 1)) + bk], w);
    }
    __syncthreads();

    // ---- GEMM: out[c,:] = sum_k coef[c,k] * x[srcs[c,k]] @ W[k] (bf16x3) ----
    // 16 warps: wm = wid&1 (2 x 32 rows), wn = wid>>1 (8 x 16 cols)
    const int wm = wid & 1;
    const int wn = wid >> 1;
    const uint32_t a_off[2] = {
        (uint32_t)(AH_OFF + (wm * 32 + 0  + (lane & 15)) * LDB + (lane >> 4) * 16),
        (uint32_t)(AH_OFF + (wm * 32 + 16 + (lane & 15)) * LDB + (lane >> 4) * 16)};
    const uint32_t b_off =
        (uint32_t)(BH_OFF + (wn * 16 + ((lane >> 4) << 3) + (lane & 7)) * LDB
                   + ((lane >> 3) & 1) * 16);
    const uint32_t AL_DELTA = A_BYTES;   // AH -> AL
    const uint32_t BL_DELTA = B_BYTES;   // BH -> BL

    float acc[2][2][4];
    #pragma unroll
    for (int mt = 0; mt < 2; mt++)
        #pragma unroll
        for (int nt = 0; nt < 2; nt++)
            #pragma unroll
            for (int q = 0; q < 4; q++) acc[mt][nt][q] = 0.0f;

    // A staging: thread owns row tid>>3, 8-float chunk (tid&7)
    const int arow = tid >> 3;
    const int aq   = tid & 7;
    float4 av[2];
    float  asc;
    uint4  bv[4];   // 2 hi + 2 lo 16B chunks

    // prologue: load k=0 into registers
    {
        int src = s_srcs[arow * PK + 0];
        asc = s_coef[arow * PK + 0];
        const float4* xp = (const float4*)(x + (size_t)src * IN_F + aq * 8);
        av[0] = xp[0]; av[1] = xp[1];
        const char* wh = (const char*)g_wt_hi;
        const char* wl = (const char*)g_wt_lo;
        #pragma unroll
        for (int j = 0; j < 2; j++) {
            int g = tid + j * NTH;
            int row = g >> 3, cch = g & 7;
            bv[j]     = *(const uint4*)(wh + row * 128 + cch * 16);
            bv[j + 2] = *(const uint4*)(wl + row * 128 + cch * 16);
        }
    }

    #pragma unroll 1
    for (int k = 0; k < PK; k++) {
        // ---- store regs (data for step k) into smem ----
        {
            float fv[8];
            fv[0] = av[0].x * asc; fv[1] = av[0].y * asc;
            fv[2] = av[0].z * asc; fv[3] = av[0].w * asc;
            fv[4] = av[1].x * asc; fv[5] = av[1].y * asc;
            fv[6] = av[1].z * asc; fv[7] = av[1].w * asc;
            uint32_t hi[4], lo[4];
            #pragma unroll
            for (int e2 = 0; e2 < 4; e2++) {
                float f0 = fv[e2 * 2], f1 = fv[e2 * 2 + 1];
                __nv_bfloat16 h0 = __float2bfloat16(f0);
                __nv_bfloat16 h1 = __float2bfloat16(f1);
                __nv_bfloat162 hp; hp.x = h0; hp.y = h1;
                __nv_bfloat162 lp;
                lp.x = __float2bfloat16(f0 - __bfloat162float(h0));
                lp.y = __float2bfloat16(f1 - __bfloat162float(h1));
                hi[e2] = *(uint32_t*)&hp;
                lo[e2] = *(uint32_t*)&lp;
            }
            *(uint4*)(sm + AH_OFF + arow * LDB + aq * 16) =
                make_uint4(hi[0], hi[1], hi[2], hi[3]);
            *(uint4*)(sm + AL_OFF + arow * LDB + aq * 16) =
                make_uint4(lo[0], lo[1], lo[2], lo[3]);
            #pragma unroll
            for (int j = 0; j < 2; j++) {
                int g = tid + j * NTH;
                int row = g >> 3, cch = g & 7;
                *(uint4*)(sm + BH_OFF + row * LDB + cch * 16) = bv[j];
                *(uint4*)(sm + BL_OFF + row * LDB + cch * 16) = bv[j + 2];
            }
        }
        __syncthreads();

        // ---- issue next step's global loads (outstanding across compute) ----
        if (k + 1 < PK) {
            int src = s_srcs[arow * PK + k + 1];
            asc = s_coef[arow * PK + k + 1];
            const float4* xp = (const float4*)(x + (size_t)src * IN_F + aq * 8);
            av[0] = xp[0]; av[1] = xp[1];
            const char* wh = (const char*)g_wt_hi + (size_t)(k + 1) * (OUT_F * IN_F * 2);
            const char* wl = (const char*)g_wt_lo + (size_t)(k + 1) * (OUT_F * IN_F * 2);
            #pragma unroll
            for (int j = 0; j < 2; j++) {
                int g = tid + j * NTH;
                int row = g >> 3, cch = g & 7;
                bv[j]     = *(const uint4*)(wh + row * 128 + cch * 16);
                bv[j + 2] = *(const uint4*)(wl + row * 128 + cch * 16);
            }
        }

        // ---- compute on smem tiles ----
        #pragma unroll
        for (int ks = 0; ks < 4; ks++) {
            const uint32_t i0 = ks * 32;   // 16 bf16 = 32 bytes
            uint32_t ah[2][4], al[2][4], bh[4], bl[4];
            #pragma unroll
            for (int mt = 0; mt < 2; mt++) {
                ldsm4(ah[mt], smb + a_off[mt] + i0);
                ldsm4(al[mt], smb + a_off[mt] + AL_DELTA + i0);
            }
            ldsm4(bh, smb + b_off + i0);
            ldsm4(bl, smb + b_off + BL_DELTA + i0);
            #pragma unroll
            for (int mt = 0; mt < 2; mt++)
                #pragma unroll
                for (int nt = 0; nt < 2; nt++) {
                    const uint32_t* bhf = &bh[nt * 2];
                    const uint32_t* blf = &bl[nt * 2];
                    mma_bf16(acc[mt][nt], ah[mt], bhf);
                    mma_bf16(acc[mt][nt], ah[mt], blf);
                    mma_bf16(acc[mt][nt], al[mt], bhf);
                }
        }
        __syncthreads();
    }

    // ---- epilogue: direct f32 stores ----------------------------------------
    #pragma unroll
    for (int mt = 0; mt < 2; mt++) {
        int row = c0 + wm * 32 + mt * 16 + (lane >> 2);
        #pragma unroll
        for (int nt = 0; nt < 2; nt++) {
            int col = wn * 16 + nt * 8 + (lane & 3) * 2;
            float2 v0 = make_float2(acc[mt][nt][0], acc[mt][nt][1]);
            float2 v1 = make_float2(acc[mt][nt][2], acc[mt][nt][3]);
            *(float2*)(out + (size_t)row * OUT_F + col)       = v0;
            *(float2*)(out + (size_t)(row + 8) * OUT_F + col) = v1;
        }
    }
}

extern "C" void kernel_launch(void* const* d_in, const int* in_sizes, int n_in,
                              void* d_out, int out_size) {
    const float* x             = (const float*)d_in[0];
    const float* pos           = (const float*)d_in[1];
    const int*   edge_src      = (const int*)d_in[2];
    const int*   edge_tgt      = (const int*)d_in[3];
    const float* kernel_pts    = (const float*)d_in[4];
    const float* kernel_weight = (const float*)d_in[5];
    float* out = (float*)d_out;

    wsplit_kernel<<<(PK * OUT_F * IN_F + 255) / 256, 256>>>(kernel_weight);

    cudaFuncSetAttribute(kpconv_hmma_kernel,
                         cudaFuncAttributeMaxDynamicSharedMemorySize, SM_TOTAL);
    kpconv_hmma_kernel<<<NCENT / M_TILE, NTH, SM_TOTAL>>>(
        x, pos, edge_src, edge_tgt, kernel_pts, out);
}

// round 8
// speedup vs baseline: 1.0495x; 1.0495x over previous
#include <cuda_runtime.h>
#include <cuda_bf16.h>
#include <cstdint>

#define PK      16
#define NCENT   8192
#define IN_F    64
#define OUT_F   128
#define M_TILE  64
#define NTH     512
#define LDB     144          // A smem row pitch bytes (64 bf16 + 8 pad)

// B packed in mma-fragment order (PTX m16n8k16 .col B frag):
// index = k*8192 + wn*1024 + nt*512 + sel*256 + lane*8 + r   (u32 units)
//   r = ks*2 + pair;  element = bf16x2{ W[k][i][o], W[k][i+1][o] }
//   o = wn*16 + nt*8 + (lane>>2);  i = ks*16 + (lane&3)*2 + pair*8
//   sel: 0 = hi bf16(v), 1 = lo bf16(v - hi)
__device__ __align__(128) uint32_t g_bfrag[PK * 8 * 2 * 2 * 32 * 8];   // 512KB

// ---------------- smem layout (bytes): A double-buffered, 45.5KB ------------
#define SM_KPTS   0                        // 48 floats
#define SM_COEF   256                      // 64*16 f32 = 4096
#define SM_SRCS   (SM_COEF + 4096)         // 64*16 int = 4096
#define SM_A      8704
#define A_BYTES   (M_TILE * LDB)           // 9216
#define AH_OFF(s) (SM_A + (s) * 2 * A_BYTES)
#define AL_OFF(s) (AH_OFF(s) + A_BYTES)
#define SM_TOTAL  (SM_A + 4 * A_BYTES)     // 45568

// ---------------- PTX helpers ------------------------------------------------
__device__ __forceinline__ uint32_t smem_u32(const void* p) {
    uint32_t a;
    asm("{ .reg .u64 t; cvta.to.shared.u64 t, %1; cvt.u32.u64 %0, t; }"
        : "=r"(a) : "l"(p));
    return a;
}
__device__ __forceinline__ void ldsm4(uint32_t* r, uint32_t addr) {
    asm volatile("ldmatrix.sync.aligned.m8n8.x4.shared.b16 {%0,%1,%2,%3}, [%4];"
                 : "=r"(r[0]), "=r"(r[1]), "=r"(r[2]), "=r"(r[3]) : "r"(addr));
}
__device__ __forceinline__ void mma_bf16(float* c, const uint32_t* a, const uint32_t* b) {
    asm volatile("mma.sync.aligned.m16n8k16.row.col.f32.bf16.bf16.f32 "
                 "{%0,%1,%2,%3}, {%4,%5,%6,%7}, {%8,%9}, {%0,%1,%2,%3};"
                 : "+f"(c[0]), "+f"(c[1]), "+f"(c[2]), "+f"(c[3])
                 : "r"(a[0]), "r"(a[1]), "r"(a[2]), "r"(a[3]),
                   "r"(b[0]), "r"(b[1]));
}

// ---------------- pre-kernel: W -> fragment-packed hi/lo ---------------------
__global__ void wpack_kernel(const float* __restrict__ w) {
    int idx = blockIdx.x * blockDim.x + threadIdx.x;
    if (idx >= PK * 8 * 2 * 2 * 32 * 8) return;     // 131072
    int r    = idx & 7;
    int lane = (idx >> 3) & 31;
    int sel  = (idx >> 8) & 1;
    int nt   = (idx >> 9) & 1;
    int wn   = (idx >> 10) & 7;
    int k    = idx >> 13;
    int ks   = r >> 1;
    int pair = r & 1;
    int o = wn * 16 + nt * 8 + (lane >> 2);
    int i = ks * 16 + (lane & 3) * 2 + pair * 8;
    float v0 = w[k * (IN_F * OUT_F) + i * OUT_F + o];
    float v1 = w[k * (IN_F * OUT_F) + (i + 1) * OUT_F + o];
    __nv_bfloat16 h0 = __float2bfloat16(v0);
    __nv_bfloat16 h1 = __float2bfloat16(v1);
    if (sel) {
        h0 = __float2bfloat16(v0 - __bfloat162float(h0));
        h1 = __float2bfloat16(v1 - __bfloat162float(h1));
    }
    __nv_bfloat162 p; p.x = h0; p.y = h1;
    g_bfrag[idx] = *(uint32_t*)&p;
}

// ---------------- main fused kernel ------------------------------------------
__global__ __launch_bounds__(NTH, 1) void kpconv_hmma_kernel(
    const float* __restrict__ x,
    const float* __restrict__ pos,
    const int*   __restrict__ edge_src,
    const int*   __restrict__ edge_tgt,
    const float* __restrict__ kernel_pts,
    float* __restrict__ out)
{
    extern __shared__ char sm[];
    const uint32_t smb = smem_u32(sm);
    float* s_kpts = (float*)(sm + SM_KPTS);
    float* s_coef = (float*)(sm + SM_COEF);
    int*   s_srcs = (int*)(sm + SM_SRCS);

    const int tid  = threadIdx.x;
    const int wid  = tid >> 5;
    const int lane = tid & 31;
    const int c0   = blockIdx.x * M_TILE;

    if (tid < PK * 3) s_kpts[tid] = kernel_pts[tid];
    for (int i = tid; i < M_TILE * PK; i += NTH) s_coef[i] = 0.0f;
    __syncthreads();

    // ---- geometry: argmin kernel point + linear influence -> coef/srcs -----
    #pragma unroll
    for (int j = 0; j < (M_TILE * PK) / NTH; j++) {
        int el = tid + j * NTH;
        int e  = c0 * PK + el;
        int s  = edge_src[e];
        int t  = edge_tgt[e];
        s_srcs[el] = s;
        float rx = pos[3 * t + 0] - pos[3 * s + 0];
        float ry = pos[3 * t + 1] - pos[3 * s + 1];
        float rz = pos[3 * t + 2] - pos[3 * s + 2];
        float best = 3.4e38f; int bk = 0;
        #pragma unroll
        for (int kp = 0; kp < PK; kp++) {
            float dx = rx - s_kpts[3 * kp + 0];
            float dy = ry - s_kpts[3 * kp + 1];
            float dz = rz - s_kpts[3 * kp + 2];
            float d2 = dx * dx + dy * dy + dz * dz;
            if (d2 < best) { best = d2; bk = kp; }
        }
        float w = fmaxf(1.0f - sqrtf(best) * 1.5f, 0.0f);   // 1/KP_EXTENT = 1.5
        atomicAdd(&s_coef[(el & ~(PK - 1)) + bk], w);
    }
    __syncthreads();

    // ---- GEMM: out[c,:] = sum_k coef[c,k] * x[srcs[c,k]] @ W[k] (bf16x3) ----
    const int wm = wid & 1;           // 2 x 32 rows
    const int wn = wid >> 1;          // 8 x 16 cols
    const uint32_t a_row_off[2] = {
        (uint32_t)((wm * 32 + 0  + (lane & 15)) * LDB + (lane >> 4) * 16),
        (uint32_t)((wm * 32 + 16 + (lane & 15)) * LDB + (lane >> 4) * 16)};

    float acc[2][2][4];
    #pragma unroll
    for (int mt = 0; mt < 2; mt++)
        #pragma unroll
        for (int nt = 0; nt < 2; nt++)
            #pragma unroll
            for (int q = 0; q < 4; q++) acc[mt][nt][q] = 0.0f;

    // A staging: thread owns row tid>>3, 8-float chunk (tid&7)
    const int arow = tid >> 3;
    const int aq   = tid & 7;
    float4 av[2];
    float  asc;

    // helper lambda-free A convert+store
    #define A_CVT_STORE(stage)                                                  \
        do {                                                                    \
            float fv[8];                                                        \
            fv[0] = av[0].x * asc; fv[1] = av[0].y * asc;                       \
            fv[2] = av[0].z * asc; fv[3] = av[0].w * asc;                       \
            fv[4] = av[1].x * asc; fv[5] = av[1].y * asc;                       \
            fv[6] = av[1].z * asc; fv[7] = av[1].w * asc;                       \
            uint32_t hi[4], lo[4];                                              \
            _Pragma("unroll")                                                   \
            for (int e2 = 0; e2 < 4; e2++) {                                    \
                float f0 = fv[e2 * 2], f1 = fv[e2 * 2 + 1];                     \
                __nv_bfloat16 h0 = __float2bfloat16(f0);                        \
                __nv_bfloat16 h1 = __float2bfloat16(f1);                        \
                __nv_bfloat162 hp; hp.x = h0; hp.y = h1;                        \
                __nv_bfloat162 lp;                                              \
                lp.x = __float2bfloat16(f0 - __bfloat162float(h0));             \
                lp.y = __float2bfloat16(f1 - __bfloat162float(h1));             \
                hi[e2] = *(uint32_t*)&hp;                                       \
                lo[e2] = *(uint32_t*)&lp;                                       \
            }                                                                   \
            *(uint4*)(sm + AH_OFF(stage) + arow * LDB + aq * 16) =              \
                make_uint4(hi[0], hi[1], hi[2], hi[3]);                         \
            *(uint4*)(sm + AL_OFF(stage) + arow * LDB + aq * 16) =              \
                make_uint4(lo[0], lo[1], lo[2], lo[3]);                         \
        } while (0)

    // prologue: gather + stage A[0] into buffer 0
    {
        int src = s_srcs[arow * PK + 0];
        asc = s_coef[arow * PK + 0];
        const float4* xp = (const float4*)(x + (size_t)src * IN_F + aq * 8);
        av[0] = xp[0]; av[1] = xp[1];
        A_CVT_STORE(0);
    }
    __syncthreads();

    #pragma unroll 1
    for (int k = 0; k < PK; k++) {
        const int cur = k & 1;
        const int nxt = cur ^ 1;

        // ---- issue A[k+1] gather early (outstanding across compute) ----
        if (k + 1 < PK) {
            int src = s_srcs[arow * PK + k + 1];
            asc = s_coef[arow * PK + k + 1];
            const float4* xp = (const float4*)(x + (size_t)src * IN_F + aq * 8);
            av[0] = xp[0]; av[1] = xp[1];
        }

        // ---- B fragments: coalesced LDG.128 straight to registers ----
        const uint32_t* bbase = g_bfrag + k * 8192 + wn * 1024 + lane * 8;
        uint4 h0a = *(const uint4*)(bbase);
        uint4 h0b = *(const uint4*)(bbase + 4);
        uint4 l0a = *(const uint4*)(bbase + 256);
        uint4 l0b = *(const uint4*)(bbase + 260);
        uint4 h1a = *(const uint4*)(bbase + 512);
        uint4 h1b = *(const uint4*)(bbase + 516);
        uint4 l1a = *(const uint4*)(bbase + 768);
        uint4 l1b = *(const uint4*)(bbase + 772);
        uint32_t bh[2][8] = {
            {h0a.x, h0a.y, h0a.z, h0a.w, h0b.x, h0b.y, h0b.z, h0b.w},
            {h1a.x, h1a.y, h1a.z, h1a.w, h1b.x, h1b.y, h1b.z, h1b.w}};
        uint32_t bl[2][8] = {
            {l0a.x, l0a.y, l0a.z, l0a.w, l0b.x, l0b.y, l0b.z, l0b.w},
            {l1a.x, l1a.y, l1a.z, l1a.w, l1b.x, l1b.y, l1b.z, l1b.w}};

        // ---- compute on A stage cur ----
        const uint32_t ah_b = smb + AH_OFF(cur);
        const uint32_t al_b = smb + AL_OFF(cur);
        #pragma unroll
        for (int ks = 0; ks < 4; ks++) {
            const uint32_t i0 = ks * 32;
            uint32_t ah[2][4], al[2][4];
            #pragma unroll
            for (int mt = 0; mt < 2; mt++) {
                ldsm4(ah[mt], ah_b + a_row_off[mt] + i0);
                ldsm4(al[mt], al_b + a_row_off[mt] + i0);
            }
            #pragma unroll
            for (int mt = 0; mt < 2; mt++)
                #pragma unroll
                for (int nt = 0; nt < 2; nt++) {
                    mma_bf16(acc[mt][nt], ah[mt], &bh[nt][ks * 2]);
                    mma_bf16(acc[mt][nt], ah[mt], &bl[nt][ks * 2]);
                    mma_bf16(acc[mt][nt], al[mt], &bh[nt][ks * 2]);
                }
        }

        // ---- convert + store A[k+1] into stage nxt, single barrier ----
        if (k + 1 < PK) A_CVT_STORE(nxt);
        __syncthreads();
    }

    // ---- epilogue: direct f32 stores ----------------------------------------
    #pragma unroll
    for (int mt = 0; mt < 2; mt++) {
        int row = c0 + wm * 32 + mt * 16 + (lane >> 2);
        #pragma unroll
        for (int nt = 0; nt < 2; nt++) {
            int col = wn * 16 + nt * 8 + (lane & 3) * 2;
            float2 v0 = make_float2(acc[mt][nt][0], acc[mt][nt][1]);
            float2 v1 = make_float2(acc[mt][nt][2], acc[mt][nt][3]);
            *(float2*)(out + (size_t)row * OUT_F + col)       = v0;
            *(float2*)(out + (size_t)(row + 8) * OUT_F + col) = v1;
        }
    }
}

extern "C" void kernel_launch(void* const* d_in, const int* in_sizes, int n_in,
                              void* d_out, int out_size) {
    const float* x             = (const float*)d_in[0];
    const float* pos           = (const float*)d_in[1];
    const int*   edge_src      = (const int*)d_in[2];
    const int*   edge_tgt      = (const int*)d_in[3];
    const float* kernel_pts    = (const float*)d_in[4];
    const float* kernel_weight = (const float*)d_in[5];
    float* out = (float*)d_out;

    wpack_kernel<<<(PK * 8 * 2 * 2 * 32 * 8 + 255) / 256, 256>>>(kernel_weight);

    cudaFuncSetAttribute(kpconv_hmma_kernel,
                         cudaFuncAttributeMaxDynamicSharedMemorySize, SM_TOTAL);
    kpconv_hmma_kernel<<<NCENT / M_TILE, NTH, SM_TOTAL>>>(
        x, pos, edge_src, edge_tgt, kernel_pts, out);
}

// round 9
// speedup vs baseline: 1.1969x; 1.1405x over previous
#include <cuda_runtime.h>
#include <cuda_bf16.h>
#include <cstdint>

#define PK      16
#define NCENT   8192
#define IN_F    64
#define OUT_F   128
#define M_TILE  64
#define NTH     512
#define LDB     144          // A smem row pitch bytes (64 bf16 + 8 pad)

// B packed in mma-fragment order (PTX m16n8k16 .col B frag):
// index = k*8192 + wn*1024 + nt*512 + sel*256 + lane*8 + r   (u32 units)
__device__ __align__(128) uint32_t g_bfrag[PK * 8 * 2 * 2 * 32 * 8];   // 512KB

// ---------------- smem layout (bytes): A double-buffered, 45.5KB ------------
#define SM_KPTS   0
#define SM_COEF   256
#define SM_SRCS   (SM_COEF + 4096)
#define SM_A      8704
#define A_BYTES   (M_TILE * LDB)           // 9216
#define AH_OFF(s) (SM_A + (s) * 2 * A_BYTES)
#define AL_OFF(s) (AH_OFF(s) + A_BYTES)
#define SM_TOTAL  (SM_A + 4 * A_BYTES)     // 45568

__device__ __forceinline__ uint32_t smem_u32(const void* p) {
    uint32_t a;
    asm("{ .reg .u64 t; cvta.to.shared.u64 t, %1; cvt.u32.u64 %0, t; }"
        : "=r"(a) : "l"(p));
    return a;
}
__device__ __forceinline__ void ldsm4(uint32_t* r, uint32_t addr) {
    asm volatile("ldmatrix.sync.aligned.m8n8.x4.shared.b16 {%0,%1,%2,%3}, [%4];"
                 : "=r"(r[0]), "=r"(r[1]), "=r"(r[2]), "=r"(r[3]) : "r"(addr));
}
__device__ __forceinline__ void mma_bf16(float* c, const uint32_t* a, const uint32_t* b) {
    asm volatile("mma.sync.aligned.m16n8k16.row.col.f32.bf16.bf16.f32 "
                 "{%0,%1,%2,%3}, {%4,%5,%6,%7}, {%8,%9}, {%0,%1,%2,%3};"
                 : "+f"(c[0]), "+f"(c[1]), "+f"(c[2]), "+f"(c[3])
                 : "r"(a[0]), "r"(a[1]), "r"(a[2]), "r"(a[3]),
                   "r"(b[0]), "r"(b[1]));
}

// ---------------- pre-kernel: W -> fragment-packed hi/lo ---------------------
__global__ void wpack_kernel(const float* __restrict__ w) {
    int idx = blockIdx.x * blockDim.x + threadIdx.x;
    if (idx >= PK * 8 * 2 * 2 * 32 * 8) return;
    int r    = idx & 7;
    int lane = (idx >> 3) & 31;
    int sel  = (idx >> 8) & 1;
    int nt   = (idx >> 9) & 1;
    int wn   = (idx >> 10) & 7;
    int k    = idx >> 13;
    int ks   = r >> 1;
    int pair = r & 1;
    int o = wn * 16 + nt * 8 + (lane >> 2);
    int i = ks * 16 + (lane & 3) * 2 + pair * 8;
    float v0 = w[k * (IN_F * OUT_F) + i * OUT_F + o];
    float v1 = w[k * (IN_F * OUT_F) + (i + 1) * OUT_F + o];
    __nv_bfloat16 h0 = __float2bfloat16(v0);
    __nv_bfloat16 h1 = __float2bfloat16(v1);
    if (sel) {
        h0 = __float2bfloat16(v0 - __bfloat162float(h0));
        h1 = __float2bfloat16(v1 - __bfloat162float(h1));
    }
    __nv_bfloat162 p; p.x = h0; p.y = h1;
    g_bfrag[idx] = *(uint32_t*)&p;
}

#define A_CVT_STORE(stage)                                                  \
    do {                                                                    \
        float fv[8];                                                        \
        fv[0] = av[0].x * asc; fv[1] = av[0].y * asc;                       \
        fv[2] = av[0].z * asc; fv[3] = av[0].w * asc;                       \
        fv[4] = av[1].x * asc; fv[5] = av[1].y * asc;                       \
        fv[6] = av[1].z * asc; fv[7] = av[1].w * asc;                       \
        uint32_t hi[4], lo[4];                                              \
        _Pragma("unroll")                                                   \
        for (int e2 = 0; e2 < 4; e2++) {                                    \
            float f0 = fv[e2 * 2], f1 = fv[e2 * 2 + 1];                     \
            __nv_bfloat16 h0 = __float2bfloat16(f0);                        \
            __nv_bfloat16 h1 = __float2bfloat16(f1);                        \
            __nv_bfloat162 hp; hp.x = h0; hp.y = h1;                        \
            __nv_bfloat162 lp;                                              \
            lp.x = __float2bfloat16(f0 - __bfloat162float(h0));             \
            lp.y = __float2bfloat16(f1 - __bfloat162float(h1));             \
            hi[e2] = *(uint32_t*)&hp;                                       \
            lo[e2] = *(uint32_t*)&lp;                                       \
        }                                                                   \
        *(uint4*)(sm + AH_OFF(stage) + arow * LDB + aq * 16) =              \
            make_uint4(hi[0], hi[1], hi[2], hi[3]);                         \
        *(uint4*)(sm + AL_OFF(stage) + arow * LDB + aq * 16) =              \
            make_uint4(lo[0], lo[1], lo[2], lo[3]);                         \
    } while (0)

// one pipelined k-step: prefetch A/B for k+1, compute k from bcur, stage A
struct StepCtx {
    char* sm; uint32_t smb;
    const float* x; const int* s_srcs; const float* s_coef;
    int arow, aq, wn, lane;
    uint32_t a_row_off0, a_row_off1;
};

__device__ __forceinline__ void gemm_step(
    int k, uint4 (&bcur)[8], uint4 (&bnxt)[8],
    const StepCtx& c, float4 (&av)[2], float& asc,
    float (&acc)[2][2][4])
{
    char* sm = c.sm;
    const int arow = c.arow, aq = c.aq;
    const int cur = k & 1;

    // prefetch A[k+1] + B[k+1] (LDGs outstanding across compute)
    if (k + 1 < PK) {
        int src = c.s_srcs[arow * PK + k + 1];
        asc = c.s_coef[arow * PK + k + 1];
        const float4* xp = (const float4*)(c.x + (size_t)src * IN_F + aq * 8);
        av[0] = xp[0]; av[1] = xp[1];
        const uint32_t* bb = g_bfrag + (k + 1) * 8192 + c.wn * 1024 + c.lane * 8;
        bnxt[0] = *(const uint4*)(bb + 0);
        bnxt[1] = *(const uint4*)(bb + 4);
        bnxt[2] = *(const uint4*)(bb + 256);
        bnxt[3] = *(const uint4*)(bb + 260);
        bnxt[4] = *(const uint4*)(bb + 512);
        bnxt[5] = *(const uint4*)(bb + 516);
        bnxt[6] = *(const uint4*)(bb + 768);
        bnxt[7] = *(const uint4*)(bb + 772);
    }

    // unpack current B fragments (register aliases, no traffic)
    uint32_t bh[2][8] = {
        {bcur[0].x, bcur[0].y, bcur[0].z, bcur[0].w,
         bcur[1].x, bcur[1].y, bcur[1].z, bcur[1].w},
        {bcur[4].x, bcur[4].y, bcur[4].z, bcur[4].w,
         bcur[5].x, bcur[5].y, bcur[5].z, bcur[5].w}};
    uint32_t bl[2][8] = {
        {bcur[2].x, bcur[2].y, bcur[2].z, bcur[2].w,
         bcur[3].x, bcur[3].y, bcur[3].z, bcur[3].w},
        {bcur[6].x, bcur[6].y, bcur[6].z, bcur[6].w,
         bcur[7].x, bcur[7].y, bcur[7].z, bcur[7].w}};

    const uint32_t ah_b = c.smb + AH_OFF(cur);
    const uint32_t al_b = c.smb + AL_OFF(cur);
    const uint32_t aro[2] = {c.a_row_off0, c.a_row_off1};
    #pragma unroll
    for (int ks = 0; ks < 4; ks++) {
        const uint32_t i0 = ks * 32;
        uint32_t ah[2][4], al[2][4];
        #pragma unroll
        for (int mt = 0; mt < 2; mt++) {
            ldsm4(ah[mt], ah_b + aro[mt] + i0);
            ldsm4(al[mt], al_b + aro[mt] + i0);
        }
        #pragma unroll
        for (int mt = 0; mt < 2; mt++)
            #pragma unroll
            for (int nt = 0; nt < 2; nt++) {
                mma_bf16(acc[mt][nt], ah[mt], &bh[nt][ks * 2]);
                mma_bf16(acc[mt][nt], ah[mt], &bl[nt][ks * 2]);
                mma_bf16(acc[mt][nt], al[mt], &bh[nt][ks * 2]);
            }
    }

    if (k + 1 < PK) A_CVT_STORE(cur ^ 1);
    __syncthreads();
}

// ---------------- main fused kernel ------------------------------------------
__global__ __launch_bounds__(NTH, 1) void kpconv_hmma_kernel(
    const float* __restrict__ x,
    const float* __restrict__ pos,
    const int*   __restrict__ edge_src,
    const int*   __restrict__ edge_tgt,
    const float* __restrict__ kernel_pts,
    float* __restrict__ out)
{
    extern __shared__ char sm[];
    const uint32_t smb = smem_u32(sm);
    float* s_kpts = (float*)(sm + SM_KPTS);
    float* s_coef = (float*)(sm + SM_COEF);
    int*   s_srcs = (int*)(sm + SM_SRCS);

    const int tid  = threadIdx.x;
    const int wid  = tid >> 5;
    const int lane = tid & 31;
    const int c0   = blockIdx.x * M_TILE;

    if (tid < PK * 3) s_kpts[tid] = kernel_pts[tid];
    for (int i = tid; i < M_TILE * PK; i += NTH) s_coef[i] = 0.0f;
    __syncthreads();

    // ---- geometry ----
    #pragma unroll
    for (int j = 0; j < (M_TILE * PK) / NTH; j++) {
        int el = tid + j * NTH;
        int e  = c0 * PK + el;
        int s  = edge_src[e];
        int t  = edge_tgt[e];
        s_srcs[el] = s;
        float rx = pos[3 * t + 0] - pos[3 * s + 0];
        float ry = pos[3 * t + 1] - pos[3 * s + 1];
        float rz = pos[3 * t + 2] - pos[3 * s + 2];
        float best = 3.4e38f; int bk = 0;
        #pragma unroll
        for (int kp = 0; kp < PK; kp++) {
            float dx = rx - s_kpts[3 * kp + 0];
            float dy = ry - s_kpts[3 * kp + 1];
            float dz = rz - s_kpts[3 * kp + 2];
            float d2 = dx * dx + dy * dy + dz * dz;
            if (d2 < best) { best = d2; bk = kp; }
        }
        float w = fmaxf(1.0f - sqrtf(best) * 1.5f, 0.0f);
        atomicAdd(&s_coef[(el & ~(PK - 1)) + bk], w);
    }
    __syncthreads();

    const int wm = wid & 1;
    const int wn = wid >> 1;

    StepCtx ctx;
    ctx.sm = sm; ctx.smb = smb;
    ctx.x = x; ctx.s_srcs = s_srcs; ctx.s_coef = s_coef;
    ctx.arow = tid >> 3; ctx.aq = tid & 7; ctx.wn = wn; ctx.lane = lane;
    ctx.a_row_off0 = (uint32_t)((wm * 32 + 0  + (lane & 15)) * LDB + (lane >> 4) * 16);
    ctx.a_row_off1 = (uint32_t)((wm * 32 + 16 + (lane & 15)) * LDB + (lane >> 4) * 16);

    float acc[2][2][4];
    #pragma unroll
    for (int mt = 0; mt < 2; mt++)
        #pragma unroll
        for (int nt = 0; nt < 2; nt++)
            #pragma unroll
            for (int q = 0; q < 4; q++) acc[mt][nt][q] = 0.0f;

    const int arow = ctx.arow, aq = ctx.aq;
    float4 av[2];
    float  asc;
    uint4  b0[8], b1[8];

    // prologue: A[0] staged, B[0] -> b0
    {
        int src = s_srcs[arow * PK + 0];
        asc = s_coef[arow * PK + 0];
        const float4* xp = (const float4*)(x + (size_t)src * IN_F + aq * 8);
        av[0] = xp[0]; av[1] = xp[1];
        const uint32_t* bb = g_bfrag + wn * 1024 + lane * 8;
        b0[0] = *(const uint4*)(bb + 0);
        b0[1] = *(const uint4*)(bb + 4);
        b0[2] = *(const uint4*)(bb + 256);
        b0[3] = *(const uint4*)(bb + 260);
        b0[4] = *(const uint4*)(bb + 512);
        b0[5] = *(const uint4*)(bb + 516);
        b0[6] = *(const uint4*)(bb + 768);
        b0[7] = *(const uint4*)(bb + 772);
        A_CVT_STORE(0);
    }
    __syncthreads();

    #pragma unroll 1
    for (int kk = 0; kk < PK; kk += 2) {
        gemm_step(kk,     b0, b1, ctx, av, asc, acc);
        gemm_step(kk + 1, b1, b0, ctx, av, asc, acc);
    }

    // ---- epilogue ----
    #pragma unroll
    for (int mt = 0; mt < 2; mt++) {
        int row = c0 + wm * 32 + mt * 16 + (lane >> 2);
        #pragma unroll
        for (int nt = 0; nt < 2; nt++) {
            int col = wn * 16 + nt * 8 + (lane & 3) * 2;
            float2 v0 = make_float2(acc[mt][nt][0], acc[mt][nt][1]);
            float2 v1 = make_float2(acc[mt][nt][2], acc[mt][nt][3]);
            *(float2*)(out + (size_t)row * OUT_F + col)       = v0;
            *(float2*)(out + (size_t)(row + 8) * OUT_F + col) = v1;
        }
    }
}

extern "C" void kernel_launch(void* const* d_in, const int* in_sizes, int n_in,
                              void* d_out, int out_size) {
    const float* x             = (const float*)d_in[0];
    const float* pos           = (const float*)d_in[1];
    const int*   edge_src      = (const int*)d_in[2];
    const int*   edge_tgt      = (const int*)d_in[3];
    const float* kernel_pts    = (const float*)d_in[4];
    const float* kernel_weight = (const float*)d_in[5];
    float* out = (float*)d_out;

    wpack_kernel<<<(PK * 8 * 2 * 2 * 32 * 8 + 255) / 256, 256>>>(kernel_weight);

    cudaFuncSetAttribute(kpconv_hmma_kernel,
                         cudaFuncAttributeMaxDynamicSharedMemorySize, SM_TOTAL);
    kpconv_hmma_kernel<<<NCENT / M_TILE, NTH, SM_TOTAL>>>(
        x, pos, edge_src, edge_tgt, kernel_pts, out);
}